// round 16
// baseline (speedup 1.0000x reference)
#include <cuda_runtime.h>
#include <stdint.h>

#define N_NODES 100000
#define N_EDGES 3200000
#define F_IN    256
#define HID     64
#define NCLS    16

#define SCAN_TPB 512
#define SCAN_BPA ((N_NODES + SCAN_TPB - 1) / SCAN_TPB)   // 196 blocks per array
#define SCAN_GRID (2 * SCAN_BPA)                          // 392

#define G1_NB 64
#define G1_FC 64
#define EDGE_GRID 148   // 1 block/SM: minimal LTS self-contention + co-residency room

// ---------------- device scratch (no allocations allowed) ----------------
__device__ int   g_off_src[N_NODES + 1];
__device__ int   g_off_dst[N_NODES + 1];
__device__ int   g_cur_src[N_NODES];
__device__ int   g_cur_dst[N_NODES];
__device__ int   g_part[SCAN_GRID];
__device__ float g_es_t[N_EDGES];          // t sorted by src segment
__device__ float2 g_ed_ts[N_EDGES];        // (t, src) sorted by dst segment
__device__ float g_x1[(size_t)N_NODES * HID];
__device__ float g_y1[(size_t)N_NODES * HID];
__device__ float g_h1[(size_t)N_NODES * HID];
__device__ float g_y2[(size_t)N_NODES * NCLS];
__device__ float g_invS2[(size_t)N_NODES * NCLS];
__device__ float g_Wt1[F_IN * HID];
__device__ float g_Wt2[HID * NCLS];
__device__ float g_Apos1[HID], g_Aneg1[HID], g_Mk1[HID];
__device__ float g_Apos2[NCLS], g_Aneg2[NCLS], g_Mk2[NCLS];
__device__ unsigned g_text[4];             // encoded tpmax, tpmin, tnmax, tnmin
__device__ int   g_is64;                   // 1 if edge_index stored as int64

__device__ __forceinline__ unsigned fenc(float f) {
    unsigned u = __float_as_uint(f);
    return (u & 0x80000000u) ? ~u : (u | 0x80000000u);
}
__device__ __forceinline__ float fdec(unsigned u) {
    u = (u & 0x80000000u) ? (u & 0x7fffffffu) : ~u;
    return __uint_as_float(u);
}

// ---------------- init (+dtype detect in block 0) ----------------
__global__ void k_init(const int* __restrict__ ei32) {
    int i = blockIdx.x * blockDim.x + threadIdx.x;
    int stride = gridDim.x * blockDim.x;
    for (int j = i; j < N_NODES; j += stride) { g_cur_src[j] = 0; g_cur_dst[j] = 0; }
    if (blockIdx.x == 0) {
        int v = ei32[2 * threadIdx.x + 1];
        int anynz = __syncthreads_or(v != 0);
        if (threadIdx.x == 0) {
            g_is64 = (anynz == 0) ? 1 : 0;
            g_text[0] = fenc(-1e30f); g_text[1] = fenc(1e30f);
            g_text[2] = fenc(-1e30f); g_text[3] = fenc(1e30f);
        }
    }
}

// 2-edge pair loaders (e must be even; N_EDGES is even)
__device__ __forceinline__ void load_edge_pair(const int* __restrict__ ei32, int is64, int e,
                                               int& s0, int& s1, int& d0, int& d1) {
    if (is64) {
        const longlong2* p = (const longlong2*)&((const long long*)ei32)[e];
        longlong2 ss = *p;
        const longlong2* q = (const longlong2*)&((const long long*)ei32)[N_EDGES + e];
        longlong2 dd = *q;
        s0 = (int)ss.x; s1 = (int)ss.y;
        d0 = (int)dd.x; d1 = (int)dd.y;
    } else {
        int2 ss = *(const int2*)&ei32[e];
        int2 dd = *(const int2*)&ei32[N_EDGES + e];
        s0 = ss.x; s1 = ss.y;
        d0 = dd.x; d1 = dd.y;
    }
}

__global__ void k_hist(const int* __restrict__ ei32, const float* __restrict__ wm) {
    int i0 = blockIdx.x * blockDim.x + threadIdx.x;
    int stride = gridDim.x * blockDim.x;
    int is64 = g_is64;
    float tpmax = -1e30f, tpmin = 1e30f, tnmax = -1e30f, tnmin = 1e30f;
    for (int e = i0 * 2; e < N_EDGES; e += stride * 2) {
        int s0, s1, d0, d1;
        load_edge_pair(ei32, is64, e, s0, s1, d0, d1);
        atomicAdd(&g_cur_src[s0], 1);
        atomicAdd(&g_cur_src[s1], 1);
        atomicAdd(&g_cur_dst[d0], 1);
        atomicAdd(&g_cur_dst[d1], 1);
        float2 t2 = *(const float2*)&wm[e];
        if (t2.x >= 0.f) { tpmax = fmaxf(tpmax, t2.x); tpmin = fminf(tpmin, t2.x); }
        else             { tnmax = fmaxf(tnmax, t2.x); tnmin = fminf(tnmin, t2.x); }
        if (t2.y >= 0.f) { tpmax = fmaxf(tpmax, t2.y); tpmin = fminf(tpmin, t2.y); }
        else             { tnmax = fmaxf(tnmax, t2.y); tnmin = fminf(tnmin, t2.y); }
    }
    for (int o = 16; o; o >>= 1) {
        tpmax = fmaxf(tpmax, __shfl_xor_sync(0xffffffffu, tpmax, o));
        tpmin = fminf(tpmin, __shfl_xor_sync(0xffffffffu, tpmin, o));
        tnmax = fmaxf(tnmax, __shfl_xor_sync(0xffffffffu, tnmax, o));
        tnmin = fminf(tnmin, __shfl_xor_sync(0xffffffffu, tnmin, o));
    }
    if ((threadIdx.x & 31) == 0) {
        atomicMax(&g_text[0], fenc(tpmax)); atomicMin(&g_text[1], fenc(tpmin));
        atomicMax(&g_text[2], fenc(tnmax)); atomicMin(&g_text[3], fenc(tnmin));
    }
}

// ---- multi-block exclusive scan over both histograms ----
__global__ void k_scan_part() {
    int arr = blockIdx.x / SCAN_BPA;
    int b   = blockIdx.x % SCAN_BPA;
    const int* cnt = arr ? g_cur_dst : g_cur_src;
    int idx = b * SCAN_TPB + threadIdx.x;
    int v = (idx < N_NODES) ? cnt[idx] : 0;
    for (int o = 16; o; o >>= 1) v += __shfl_xor_sync(0xffffffffu, v, o);
    __shared__ int ws[SCAN_TPB / 32];
    int lane = threadIdx.x & 31, wid = threadIdx.x >> 5;
    if (lane == 0) ws[wid] = v;
    __syncthreads();
    if (wid == 0) {
        int s = (lane < SCAN_TPB / 32) ? ws[lane] : 0;
        for (int o = 16; o; o >>= 1) s += __shfl_xor_sync(0xffffffffu, s, o);
        if (lane == 0) g_part[blockIdx.x] = s;
    }
}

__global__ void k_scan_mid() {
    __shared__ int sm[SCAN_TPB];
    int tid = threadIdx.x;
    int v = (tid < SCAN_GRID) ? g_part[tid] : 0;
    sm[tid] = v;
    __syncthreads();
    for (int d = 1; d < SCAN_TPB; d <<= 1) {
        int t = (tid >= d) ? sm[tid - d] : 0;
        __syncthreads();
        sm[tid] += t;
        __syncthreads();
    }
    if (tid < SCAN_GRID) {
        int incl = sm[tid];
        int excl = incl - v;
        int base = (tid >= SCAN_BPA) ? sm[SCAN_BPA - 1] : 0;
        g_part[tid] = excl - base;
    }
}

__global__ void k_scan_final() {
    int arr = blockIdx.x / SCAN_BPA;
    int b   = blockIdx.x % SCAN_BPA;
    int* cnt = arr ? g_cur_dst : g_cur_src;
    int* off = arr ? g_off_dst : g_off_src;
    int tid = threadIdx.x;
    int idx = b * SCAN_TPB + tid;
    int v = (idx < N_NODES) ? cnt[idx] : 0;
    int lane = tid & 31, wid = tid >> 5;
    int inc = v;
    for (int o = 1; o < 32; o <<= 1) {
        int t = __shfl_up_sync(0xffffffffu, inc, o);
        if (lane >= o) inc += t;
    }
    __shared__ int ws[SCAN_TPB / 32];
    if (lane == 31) ws[wid] = inc;
    __syncthreads();
    if (wid == 0) {
        int s = (lane < SCAN_TPB / 32) ? ws[lane] : 0;
        for (int o = 1; o < SCAN_TPB / 32; o <<= 1) {
            int t = __shfl_up_sync(0xffffffffu, s, o);
            if (lane >= o) s += t;
        }
        if (lane < SCAN_TPB / 32) ws[lane] = s;
    }
    __syncthreads();
    int excl = inc - v + (wid ? ws[wid - 1] : 0) + g_part[blockIdx.x];
    if (idx < N_NODES) { off[idx] = excl; cnt[idx] = excl; }
    if (blockIdx.x == 0 && tid == 0) {
        g_off_src[N_NODES] = N_EDGES;
        g_off_dst[N_NODES] = N_EDGES;
    }
}

// fused scatter (2-edge unrolled): one edge-data read feeds both sorts
__global__ void k_scatter(const int* __restrict__ ei32, const float* __restrict__ wm) {
    int i0 = blockIdx.x * blockDim.x + threadIdx.x;
    int stride = gridDim.x * blockDim.x;
    int is64 = g_is64;
    for (int e = i0 * 2; e < N_EDGES; e += stride * 2) {
        int s0, s1, d0, d1;
        load_edge_pair(ei32, is64, e, s0, s1, d0, d1);
        float2 t2 = *(const float2*)&wm[e];
        int p0 = atomicAdd(&g_cur_src[s0], 1);
        int p1 = atomicAdd(&g_cur_src[s1], 1);
        g_es_t[p0] = t2.x;
        g_es_t[p1] = t2.y;
        int q0 = atomicAdd(&g_cur_dst[d0], 1);
        int q1 = atomicAdd(&g_cur_dst[d1], 1);
        g_ed_ts[q0] = make_float2(t2.x, __int_as_float(s0));
        g_ed_ts[q1] = make_float2(t2.y, __int_as_float(s1));
    }
}

// fused transposes: Wt1 (16384 elems) then Wt2 (1024 elems)
__global__ void k_transpose(const float* __restrict__ W1, const float* __restrict__ W2) {
    int idx = blockIdx.x * blockDim.x + threadIdx.x;
    if (idx < F_IN * HID) {
        int k = idx / F_IN, f = idx % F_IN;
        g_Wt1[f * HID + k] = W1[idx];
    } else if (idx < F_IN * HID + HID * NCLS) {
        int j = idx - F_IN * HID;
        int k = j / HID, f = j % HID;
        g_Wt2[f * NCLS + k] = W2[j];
    }
}

// fused preps: threads 0..63 layer1, threads 64..79 layer2
__global__ void k_prep(const float* __restrict__ w11, const float* __restrict__ w12,
                       const float* __restrict__ w21, const float* __restrict__ w22) {
    int tid = threadIdx.x;
    const float* w1; const float* w2; float *Apos, *Aneg, *Mk;
    int k, Hd;
    if (tid < HID) { k = tid; Hd = HID; w1 = w11; w2 = w12; Apos = g_Apos1; Aneg = g_Aneg1; Mk = g_Mk1; }
    else if (tid < HID + NCLS) { k = tid - HID; Hd = NCLS; w1 = w21; w2 = w22; Apos = g_Apos2; Aneg = g_Aneg2; Mk = g_Mk2; }
    else return;
    float ap = 0.f, an = 0.f;
    for (int j = 0; j < Hd; j++) {
        float w = w1[j];
        float a = fmaxf(w, 0.2f * w);
        float b = fminf(w, 0.2f * w);
        float v = w2[k * Hd + j];
        ap = fmaf(a, v, ap);
        an = fmaf(b, v, an);
    }
    Apos[k] = ap; Aneg[k] = an;
    float tpmax = fdec(g_text[0]), tpmin = fdec(g_text[1]);
    float tnmax = fdec(g_text[2]), tnmin = fdec(g_text[3]);
    float m = -1e30f;
    if (tpmax > -1e29f) m = fmaxf(m, (ap >= 0.f ? tpmax : tpmin) * ap);
    if (tnmin <  1e29f) m = fmaxf(m, (an >= 0.f ? tnmax : tnmin) * an);
    if (m < -1e29f) m = 0.f;
    Mk[k] = m;
}

// ---------------- k_S2: layer-2 softmax denominators (edge data only) ----------------
__global__ void k_S2() {
    int tid = threadIdx.x;
    int node = blockIdx.x * 8 + (tid >> 4);
    int k = tid & 15;
    if (node >= N_NODES) return;
    int a = g_off_src[node], b = g_off_src[node + 1];
    float Ap = g_Apos2[k], An = g_Aneg2[k], M = g_Mk2[k];
    float S = 0.f;
    int e = a;
    for (; e + 4 <= b; e += 4) {
        float t0 = __ldg(&g_es_t[e + 0]);
        float t1 = __ldg(&g_es_t[e + 1]);
        float t2 = __ldg(&g_es_t[e + 2]);
        float t3 = __ldg(&g_es_t[e + 3]);
        float e0 = __expf(fmaf(t0, (t0 >= 0.f) ? Ap : An, -M));
        float e1 = __expf(fmaf(t1, (t1 >= 0.f) ? Ap : An, -M));
        float e2 = __expf(fmaf(t2, (t2 >= 0.f) ? Ap : An, -M));
        float e3 = __expf(fmaf(t3, (t3 >= 0.f) ? Ap : An, -M));
        S += (e0 + e1) + (e2 + e3);
    }
    for (; e < b; e++) {
        float t = __ldg(&g_es_t[e]);
        S += __expf(fmaf(t, (t >= 0.f) ? Ap : An, -M));
    }
    g_invS2[(size_t)node * NCLS + k] = 1.f / (S + 1e-16f);
}

// ---------------- gemm1: two-tile smem GEMM ----------------
__global__ void k_gemm1(const float* __restrict__ x, const float* __restrict__ bias) {
    __shared__ __align__(16) float xs[G1_NB * G1_FC];   // [n][i]
    __shared__ __align__(16) float ws[G1_FC * HID];     // [i][k]
    int tid = threadIdx.x;
    int node0 = blockIdx.x * G1_NB;
    int k0 = (tid & 15) * 4, n0 = (tid >> 4) * 4;
    float acc[4][4] = {};
    for (int fc = 0; fc < F_IN; fc += G1_FC) {
        __syncthreads();
        {
            int n = tid >> 2;
            int node = node0 + n;
            const float4* src = (const float4*)&x[(size_t)node * F_IN + fc];
#pragma unroll
            for (int r = 0; r < 4; r++) {
                int i4 = (tid & 3) + r * 4;
                float4 v = (node < N_NODES) ? src[i4] : make_float4(0.f, 0.f, 0.f, 0.f);
                *(float4*)&xs[n * G1_FC + i4 * 4] = v;
            }
        }
        {
#pragma unroll
            for (int r = 0; r < 4; r++) {
                int idx = tid + r * 256;
                int i = idx >> 4, k4 = idx & 15;
                *(float4*)&ws[i * HID + k4 * 4] =
                    *(const float4*)&g_Wt1[(size_t)(fc + i) * HID + k4 * 4];
            }
        }
        __syncthreads();
#pragma unroll 2
        for (int i = 0; i < G1_FC; i += 4) {
            float4 w0 = *(const float4*)&ws[(i + 0) * HID + k0];
            float4 w1 = *(const float4*)&ws[(i + 1) * HID + k0];
            float4 w2 = *(const float4*)&ws[(i + 2) * HID + k0];
            float4 w3 = *(const float4*)&ws[(i + 3) * HID + k0];
#pragma unroll
            for (int j = 0; j < 4; j++) {
                float4 a = *(const float4*)&xs[(n0 + j) * G1_FC + i];
                acc[j][0] = fmaf(a.x, w0.x, acc[j][0]);
                acc[j][1] = fmaf(a.x, w0.y, acc[j][1]);
                acc[j][2] = fmaf(a.x, w0.z, acc[j][2]);
                acc[j][3] = fmaf(a.x, w0.w, acc[j][3]);
                acc[j][0] = fmaf(a.y, w1.x, acc[j][0]);
                acc[j][1] = fmaf(a.y, w1.y, acc[j][1]);
                acc[j][2] = fmaf(a.y, w1.z, acc[j][2]);
                acc[j][3] = fmaf(a.y, w1.w, acc[j][3]);
                acc[j][0] = fmaf(a.z, w2.x, acc[j][0]);
                acc[j][1] = fmaf(a.z, w2.y, acc[j][1]);
                acc[j][2] = fmaf(a.z, w2.z, acc[j][2]);
                acc[j][3] = fmaf(a.z, w2.w, acc[j][3]);
                acc[j][0] = fmaf(a.w, w3.x, acc[j][0]);
                acc[j][1] = fmaf(a.w, w3.y, acc[j][1]);
                acc[j][2] = fmaf(a.w, w3.z, acc[j][2]);
                acc[j][3] = fmaf(a.w, w3.w, acc[j][3]);
            }
        }
    }
    float4 bb = *(const float4*)&bias[k0];
#pragma unroll
    for (int j = 0; j < 4; j++) {
        int node = node0 + n0 + j;
        if (node < N_NODES) {
            float4 r;
            r.x = acc[j][0] + bb.x;
            r.y = acc[j][1] + bb.y;
            r.z = acc[j][2] + bb.z;
            r.w = acc[j][3] + bb.w;
            *(float4*)&g_x1[(size_t)node * HID + k0] = r;
        }
    }
}

// ---------------- gemm2: y2[n,k] = (sum_i h1[n,i]*W[k,i] + b[k]) * invS2[n,k] ----------------
__global__ void k_gemm2(const float* __restrict__ bias) {
    const int F = HID, K = NCLS;
    const int KH = K / 4;           // 4
    const int G  = 256 / KH;        // 64 groups of 2 nodes
    const int NB = G * 2;           // 128 nodes
    __shared__ __align__(16) float xs[NB * F];
    int tid = threadIdx.x;
    int node0 = blockIdx.x * NB;
    const int F4 = F / 4;
    for (int idx = tid; idx < NB * F4; idx += 256) {
        int nl = idx / F4, i4 = idx % F4;
        int node = node0 + nl;
        float4 v = (node < N_NODES) ? *(const float4*)&g_h1[(size_t)node * F + i4 * 4]
                                    : make_float4(0.f, 0.f, 0.f, 0.f);
        int g2 = nl >> 1, j = nl & 1;
        int base = (g2 * F + i4 * 4) * 2 + j;
        xs[base]     = v.x;
        xs[base + 2] = v.y;
        xs[base + 4] = v.z;
        xs[base + 6] = v.w;
    }
    __syncthreads();
    int k0 = (tid % KH) * 4, grp = tid / KH;
    const float2* xs2 = (const float2*)xs + (size_t)grp * F;
    float acc0[2] = {0, 0};
    float acc1[2] = {0, 0};
    float acc2[2] = {0, 0};
    float acc3[2] = {0, 0};
#pragma unroll 8
    for (int i = 0; i < F; i++) {
        float4 w = *(const float4*)&g_Wt2[i * K + k0];
        float2 a = xs2[i];
        acc0[0] = fmaf(a.x, w.x, acc0[0]); acc0[1] = fmaf(a.y, w.x, acc0[1]);
        acc1[0] = fmaf(a.x, w.y, acc1[0]); acc1[1] = fmaf(a.y, w.y, acc1[1]);
        acc2[0] = fmaf(a.x, w.z, acc2[0]); acc2[1] = fmaf(a.y, w.z, acc2[1]);
        acc3[0] = fmaf(a.x, w.w, acc3[0]); acc3[1] = fmaf(a.y, w.w, acc3[1]);
    }
    float4 bb = *(const float4*)&bias[k0];
#pragma unroll
    for (int j = 0; j < 2; j++) {
        int node = node0 + grp * 2 + j;
        if (node < N_NODES) {
            float4 s = *(const float4*)&g_invS2[(size_t)node * K + k0];
            float4 r;
            r.x = (acc0[j] + bb.x) * s.x;
            r.y = (acc1[j] + bb.y) * s.y;
            r.z = (acc2[j] + bb.z) * s.z;
            r.w = (acc3[j] + bb.w) * s.w;
            *(float4*)&g_y2[(size_t)node * K + k0] = r;
        }
    }
}

// ---------------- src pass (layer 1): y = x1 / S ----------------
__global__ void k_kc1() {
    const int K = HID;
    int tid = threadIdx.x;
    int node = blockIdx.x * 4 + tid / K;
    int k = tid % K;
    if (node >= N_NODES) return;
    int a = g_off_src[node], b = g_off_src[node + 1];
    float Ap = g_Apos1[k], An = g_Aneg1[k], M = g_Mk1[k];
    float S = 0.f;
    int e = a;
    for (; e + 4 <= b; e += 4) {
        float t0 = __ldg(&g_es_t[e + 0]);
        float t1 = __ldg(&g_es_t[e + 1]);
        float t2 = __ldg(&g_es_t[e + 2]);
        float t3 = __ldg(&g_es_t[e + 3]);
        float e0 = __expf(fmaf(t0, (t0 >= 0.f) ? Ap : An, -M));
        float e1 = __expf(fmaf(t1, (t1 >= 0.f) ? Ap : An, -M));
        float e2 = __expf(fmaf(t2, (t2 >= 0.f) ? Ap : An, -M));
        float e3 = __expf(fmaf(t3, (t3 >= 0.f) ? Ap : An, -M));
        S += (e0 + e1) + (e2 + e3);
    }
    for (; e < b; e++) {
        float t = __ldg(&g_es_t[e]);
        S += __expf(fmaf(t, (t >= 0.f) ? Ap : An, -M));
    }
    g_y1[(size_t)node * K + k] = g_x1[(size_t)node * K + k] / (S + 1e-16f);
}

// ---------------- dst pass: out[v,k] = sum_{e: dst=v} exp(t*c_k - Mk) * y[src,k] ----------------
template <int K, int MODE>  // MODE 0: ELU, MODE 1: log_softmax over K=16 lanes
__device__ void kd_body(const float* __restrict__ y, const float* __restrict__ Apos,
                        const float* __restrict__ Aneg, const float* __restrict__ Mk,
                        float* __restrict__ out) {
    const int NPB = 128 / K;
    int tid = threadIdx.x;
    int node = blockIdx.x * NPB + tid / K;
    int k = tid % K;
    if (node >= N_NODES) return;
    int a = g_off_dst[node], b = g_off_dst[node + 1];
    float Ap = Apos[k], An = Aneg[k], M = Mk[k];
    float acc = 0.f;
    int e = a;
    for (; e + 4 <= b; e += 4) {
        float2 ts0 = __ldg(&g_ed_ts[e + 0]);
        float2 ts1 = __ldg(&g_ed_ts[e + 1]);
        float2 ts2 = __ldg(&g_ed_ts[e + 2]);
        float2 ts3 = __ldg(&g_ed_ts[e + 3]);
        float yv0 = __ldg(&y[(size_t)__float_as_int(ts0.y) * K + k]);
        float yv1 = __ldg(&y[(size_t)__float_as_int(ts1.y) * K + k]);
        float yv2 = __ldg(&y[(size_t)__float_as_int(ts2.y) * K + k]);
        float yv3 = __ldg(&y[(size_t)__float_as_int(ts3.y) * K + k]);
        acc = fmaf(__expf(fmaf(ts0.x, (ts0.x >= 0.f) ? Ap : An, -M)), yv0, acc);
        acc = fmaf(__expf(fmaf(ts1.x, (ts1.x >= 0.f) ? Ap : An, -M)), yv1, acc);
        acc = fmaf(__expf(fmaf(ts2.x, (ts2.x >= 0.f) ? Ap : An, -M)), yv2, acc);
        acc = fmaf(__expf(fmaf(ts3.x, (ts3.x >= 0.f) ? Ap : An, -M)), yv3, acc);
    }
    for (; e < b; e++) {
        float2 ts = __ldg(&g_ed_ts[e]);
        float yv = __ldg(&y[(size_t)__float_as_int(ts.y) * K + k]);
        acc = fmaf(__expf(fmaf(ts.x, (ts.x >= 0.f) ? Ap : An, -M)), yv, acc);
    }
    if (MODE == 0) {
        out[(size_t)node * K + k] = (acc > 0.f) ? acc : expm1f(acc);
    } else {
        float m = acc;
        for (int o = 8; o; o >>= 1) m = fmaxf(m, __shfl_xor_sync(0xffffffffu, m, o, 16));
        float es = __expf(acc - m);
        float ssum = es;
        for (int o = 8; o; o >>= 1) ssum += __shfl_xor_sync(0xffffffffu, ssum, o, 16);
        out[(size_t)node * K + k] = acc - m - __logf(ssum);
    }
}
__global__ void k_kd1() { kd_body<HID, 0>(g_y1, g_Apos1, g_Aneg1, g_Mk1, g_h1); }
__global__ void k_kd2(float* __restrict__ out) { kd_body<NCLS, 1>(g_y2, g_Apos2, g_Aneg2, g_Mk2, out); }

// ---------------- launch ----------------
extern "C" void kernel_launch(void* const* d_in, const int* in_sizes, int n_in,
                              void* d_out, int out_size) {
    const float* x      = (const float*)d_in[0];
    const int*   ei32   = (const int*)d_in[1];   // int32 or int64 (detected on device)
    const float* wm     = (const float*)d_in[2];
    const float* lin1_w = (const float*)d_in[3];
    const float* lin1_b = (const float*)d_in[4];
    const float* m1w1   = (const float*)d_in[5];
    const float* m1w2   = (const float*)d_in[6];
    const float* lin2_w = (const float*)d_in[8];
    const float* lin2_b = (const float*)d_in[9];
    const float* m2w1   = (const float*)d_in[10];
    const float* m2w2   = (const float*)d_in[11];
    float* out = (float*)d_out;

    cudaStream_t s2;
    cudaStreamCreateWithFlags(&s2, cudaStreamNonBlocking);
    cudaEvent_t evFork, evScat, evS2;
    cudaEventCreateWithFlags(&evFork, cudaEventDisableTiming);
    cudaEventCreateWithFlags(&evScat, cudaEventDisableTiming);
    cudaEventCreateWithFlags(&evS2, cudaEventDisableTiming);

    // main: init (+detect) -> fork
    k_init<<<400, 512>>>(ei32);
    cudaEventRecord(evFork, 0);
    cudaStreamWaitEvent(s2, evFork, 0);

    // main: transposes + gemm1 (gemm1 co-resides with branch B)
    k_transpose<<<(F_IN * HID + HID * NCLS + 255) / 256, 256>>>(lin1_w, lin2_w);
    k_gemm1<<<(N_NODES + G1_NB - 1) / G1_NB, 256>>>(x, lin1_b);   // 3rd launch

    // branch B (stream s2): edge preprocessing (hist is ncu's 4th launch)
    k_hist<<<EDGE_GRID, 256, 0, s2>>>(ei32, wm);
    k_prep<<<1, HID + NCLS, 0, s2>>>(m1w1, m1w2, m2w1, m2w2);
    k_scan_part<<<SCAN_GRID, SCAN_TPB, 0, s2>>>();
    k_scan_mid<<<1, SCAN_TPB, 0, s2>>>();
    k_scan_final<<<SCAN_GRID, SCAN_TPB, 0, s2>>>();
    k_scatter<<<EDGE_GRID, 256, 0, s2>>>(ei32, wm);
    cudaEventRecord(evScat, s2);
    k_S2<<<(N_NODES + 7) / 8, 128, 0, s2>>>();
    cudaEventRecord(evS2, s2);

    // layer 1
    cudaStreamWaitEvent(0, evScat, 0);
    k_kc1<<<(N_NODES + 3) / 4, 256>>>();
    k_kd1<<<(N_NODES + 1) / 2, 128>>>();

    // layer 2 (kc2 folded into gemm2 epilogue via invS2 computed in branch B)
    cudaStreamWaitEvent(0, evS2, 0);
    k_gemm2<<<(N_NODES + 127) / 128, 256>>>(lin2_b);
    k_kd2<<<(N_NODES + 7) / 8, 128>>>(out);
}

// round 17
// speedup vs baseline: 1.0289x; 1.0289x over previous
#include <cuda_runtime.h>
#include <stdint.h>

#define N_NODES 100000
#define N_EDGES 3200000
#define F_IN    256
#define HID     64
#define NCLS    16

#define SCAN_TPB 512
#define SCAN_BPA ((N_NODES + SCAN_TPB - 1) / SCAN_TPB)   // 196 blocks per array
#define SCAN_GRID (2 * SCAN_BPA)                          // 392

#define G1_NB 64
#define G1_FC 64
#define EDGE_GRID 296   // 2 blocks/SM: best measured total (R15)

// ---------------- device scratch (no allocations allowed) ----------------
__device__ int   g_off_src[N_NODES + 1];
__device__ int   g_off_dst[N_NODES + 1];
__device__ int   g_cur_src[N_NODES];
__device__ int   g_cur_dst[N_NODES];
__device__ int   g_part[SCAN_GRID];
__device__ float g_es_t[N_EDGES];          // t sorted by src segment
__device__ float2 g_ed_ts[N_EDGES];        // (t, src) sorted by dst segment
__device__ float g_x1[(size_t)N_NODES * HID];
__device__ float g_y1[(size_t)N_NODES * HID];
__device__ float g_h1[(size_t)N_NODES * HID];
__device__ float g_y2[(size_t)N_NODES * NCLS];
__device__ float g_invS2[(size_t)N_NODES * NCLS];
__device__ float g_Wt1[F_IN * HID];
__device__ float g_Wt2[HID * NCLS];
__device__ float g_Apos1[HID], g_Aneg1[HID], g_Mk1[HID];
__device__ float g_Apos2[NCLS], g_Aneg2[NCLS], g_Mk2[NCLS];
__device__ unsigned g_text[4];             // encoded tpmax, tpmin, tnmax, tnmin
__device__ int   g_is64;                   // 1 if edge_index stored as int64

__device__ __forceinline__ unsigned fenc(float f) {
    unsigned u = __float_as_uint(f);
    return (u & 0x80000000u) ? ~u : (u | 0x80000000u);
}
__device__ __forceinline__ float fdec(unsigned u) {
    u = (u & 0x80000000u) ? (u & 0x7fffffffu) : ~u;
    return __uint_as_float(u);
}

// ---------------- init (+dtype detect in block 0) ----------------
__global__ void k_init(const int* __restrict__ ei32) {
    int i = blockIdx.x * blockDim.x + threadIdx.x;
    int stride = gridDim.x * blockDim.x;
    for (int j = i; j < N_NODES; j += stride) { g_cur_src[j] = 0; g_cur_dst[j] = 0; }
    if (blockIdx.x == 0) {
        int v = ei32[2 * threadIdx.x + 1];
        int anynz = __syncthreads_or(v != 0);
        if (threadIdx.x == 0) {
            g_is64 = (anynz == 0) ? 1 : 0;
            g_text[0] = fenc(-1e30f); g_text[1] = fenc(1e30f);
            g_text[2] = fenc(-1e30f); g_text[3] = fenc(1e30f);
        }
    }
}

// 2-edge pair loaders (e must be even; N_EDGES is even)
__device__ __forceinline__ void load_edge_pair(const int* __restrict__ ei32, int is64, int e,
                                               int& s0, int& s1, int& d0, int& d1) {
    if (is64) {
        const longlong2* p = (const longlong2*)&((const long long*)ei32)[e];
        longlong2 ss = *p;
        const longlong2* q = (const longlong2*)&((const long long*)ei32)[N_EDGES + e];
        longlong2 dd = *q;
        s0 = (int)ss.x; s1 = (int)ss.y;
        d0 = (int)dd.x; d1 = (int)dd.y;
    } else {
        int2 ss = *(const int2*)&ei32[e];
        int2 dd = *(const int2*)&ei32[N_EDGES + e];
        s0 = ss.x; s1 = ss.y;
        d0 = dd.x; d1 = dd.y;
    }
}

__global__ void k_hist(const int* __restrict__ ei32, const float* __restrict__ wm) {
    int i0 = blockIdx.x * blockDim.x + threadIdx.x;
    int stride = gridDim.x * blockDim.x;
    int is64 = g_is64;
    float tpmax = -1e30f, tpmin = 1e30f, tnmax = -1e30f, tnmin = 1e30f;
    for (int e = i0 * 2; e < N_EDGES; e += stride * 2) {
        int s0, s1, d0, d1;
        load_edge_pair(ei32, is64, e, s0, s1, d0, d1);
        atomicAdd(&g_cur_src[s0], 1);
        atomicAdd(&g_cur_src[s1], 1);
        atomicAdd(&g_cur_dst[d0], 1);
        atomicAdd(&g_cur_dst[d1], 1);
        float2 t2 = *(const float2*)&wm[e];
        if (t2.x >= 0.f) { tpmax = fmaxf(tpmax, t2.x); tpmin = fminf(tpmin, t2.x); }
        else             { tnmax = fmaxf(tnmax, t2.x); tnmin = fminf(tnmin, t2.x); }
        if (t2.y >= 0.f) { tpmax = fmaxf(tpmax, t2.y); tpmin = fminf(tpmin, t2.y); }
        else             { tnmax = fmaxf(tnmax, t2.y); tnmin = fminf(tnmin, t2.y); }
    }
    for (int o = 16; o; o >>= 1) {
        tpmax = fmaxf(tpmax, __shfl_xor_sync(0xffffffffu, tpmax, o));
        tpmin = fminf(tpmin, __shfl_xor_sync(0xffffffffu, tpmin, o));
        tnmax = fmaxf(tnmax, __shfl_xor_sync(0xffffffffu, tnmax, o));
        tnmin = fminf(tnmin, __shfl_xor_sync(0xffffffffu, tnmin, o));
    }
    if ((threadIdx.x & 31) == 0) {
        atomicMax(&g_text[0], fenc(tpmax)); atomicMin(&g_text[1], fenc(tpmin));
        atomicMax(&g_text[2], fenc(tnmax)); atomicMin(&g_text[3], fenc(tnmin));
    }
}

// ---- multi-block exclusive scan over both histograms ----
__global__ void k_scan_part() {
    int arr = blockIdx.x / SCAN_BPA;
    int b   = blockIdx.x % SCAN_BPA;
    const int* cnt = arr ? g_cur_dst : g_cur_src;
    int idx = b * SCAN_TPB + threadIdx.x;
    int v = (idx < N_NODES) ? cnt[idx] : 0;
    for (int o = 16; o; o >>= 1) v += __shfl_xor_sync(0xffffffffu, v, o);
    __shared__ int ws[SCAN_TPB / 32];
    int lane = threadIdx.x & 31, wid = threadIdx.x >> 5;
    if (lane == 0) ws[wid] = v;
    __syncthreads();
    if (wid == 0) {
        int s = (lane < SCAN_TPB / 32) ? ws[lane] : 0;
        for (int o = 16; o; o >>= 1) s += __shfl_xor_sync(0xffffffffu, s, o);
        if (lane == 0) g_part[blockIdx.x] = s;
    }
}

__global__ void k_scan_mid() {
    __shared__ int sm[SCAN_TPB];
    int tid = threadIdx.x;
    int v = (tid < SCAN_GRID) ? g_part[tid] : 0;
    sm[tid] = v;
    __syncthreads();
    for (int d = 1; d < SCAN_TPB; d <<= 1) {
        int t = (tid >= d) ? sm[tid - d] : 0;
        __syncthreads();
        sm[tid] += t;
        __syncthreads();
    }
    if (tid < SCAN_GRID) {
        int incl = sm[tid];
        int excl = incl - v;
        int base = (tid >= SCAN_BPA) ? sm[SCAN_BPA - 1] : 0;
        g_part[tid] = excl - base;
    }
}

__global__ void k_scan_final() {
    int arr = blockIdx.x / SCAN_BPA;
    int b   = blockIdx.x % SCAN_BPA;
    int* cnt = arr ? g_cur_dst : g_cur_src;
    int* off = arr ? g_off_dst : g_off_src;
    int tid = threadIdx.x;
    int idx = b * SCAN_TPB + tid;
    int v = (idx < N_NODES) ? cnt[idx] : 0;
    int lane = tid & 31, wid = tid >> 5;
    int inc = v;
    for (int o = 1; o < 32; o <<= 1) {
        int t = __shfl_up_sync(0xffffffffu, inc, o);
        if (lane >= o) inc += t;
    }
    __shared__ int ws[SCAN_TPB / 32];
    if (lane == 31) ws[wid] = inc;
    __syncthreads();
    if (wid == 0) {
        int s = (lane < SCAN_TPB / 32) ? ws[lane] : 0;
        for (int o = 1; o < SCAN_TPB / 32; o <<= 1) {
            int t = __shfl_up_sync(0xffffffffu, s, o);
            if (lane >= o) s += t;
        }
        if (lane < SCAN_TPB / 32) ws[lane] = s;
    }
    __syncthreads();
    int excl = inc - v + (wid ? ws[wid - 1] : 0) + g_part[blockIdx.x];
    if (idx < N_NODES) { off[idx] = excl; cnt[idx] = excl; }
    if (blockIdx.x == 0 && tid == 0) {
        g_off_src[N_NODES] = N_EDGES;
        g_off_dst[N_NODES] = N_EDGES;
    }
}

// fused scatter (2-edge unrolled): one edge-data read feeds both sorts
__global__ void k_scatter(const int* __restrict__ ei32, const float* __restrict__ wm) {
    int i0 = blockIdx.x * blockDim.x + threadIdx.x;
    int stride = gridDim.x * blockDim.x;
    int is64 = g_is64;
    for (int e = i0 * 2; e < N_EDGES; e += stride * 2) {
        int s0, s1, d0, d1;
        load_edge_pair(ei32, is64, e, s0, s1, d0, d1);
        float2 t2 = *(const float2*)&wm[e];
        int p0 = atomicAdd(&g_cur_src[s0], 1);
        int p1 = atomicAdd(&g_cur_src[s1], 1);
        g_es_t[p0] = t2.x;
        g_es_t[p1] = t2.y;
        int q0 = atomicAdd(&g_cur_dst[d0], 1);
        int q1 = atomicAdd(&g_cur_dst[d1], 1);
        g_ed_ts[q0] = make_float2(t2.x, __int_as_float(s0));
        g_ed_ts[q1] = make_float2(t2.y, __int_as_float(s1));
    }
}

// fused transposes: Wt1 (16384 elems) then Wt2 (1024 elems)
__global__ void k_transpose(const float* __restrict__ W1, const float* __restrict__ W2) {
    int idx = blockIdx.x * blockDim.x + threadIdx.x;
    if (idx < F_IN * HID) {
        int k = idx / F_IN, f = idx % F_IN;
        g_Wt1[f * HID + k] = W1[idx];
    } else if (idx < F_IN * HID + HID * NCLS) {
        int j = idx - F_IN * HID;
        int k = j / HID, f = j % HID;
        g_Wt2[f * NCLS + k] = W2[j];
    }
}

// fused preps: threads 0..63 layer1, threads 64..79 layer2
__global__ void k_prep(const float* __restrict__ w11, const float* __restrict__ w12,
                       const float* __restrict__ w21, const float* __restrict__ w22) {
    int tid = threadIdx.x;
    const float* w1; const float* w2; float *Apos, *Aneg, *Mk;
    int k, Hd;
    if (tid < HID) { k = tid; Hd = HID; w1 = w11; w2 = w12; Apos = g_Apos1; Aneg = g_Aneg1; Mk = g_Mk1; }
    else if (tid < HID + NCLS) { k = tid - HID; Hd = NCLS; w1 = w21; w2 = w22; Apos = g_Apos2; Aneg = g_Aneg2; Mk = g_Mk2; }
    else return;
    float ap = 0.f, an = 0.f;
    for (int j = 0; j < Hd; j++) {
        float w = w1[j];
        float a = fmaxf(w, 0.2f * w);
        float b = fminf(w, 0.2f * w);
        float v = w2[k * Hd + j];
        ap = fmaf(a, v, ap);
        an = fmaf(b, v, an);
    }
    Apos[k] = ap; Aneg[k] = an;
    float tpmax = fdec(g_text[0]), tpmin = fdec(g_text[1]);
    float tnmax = fdec(g_text[2]), tnmin = fdec(g_text[3]);
    float m = -1e30f;
    if (tpmax > -1e29f) m = fmaxf(m, (ap >= 0.f ? tpmax : tpmin) * ap);
    if (tnmin <  1e29f) m = fmaxf(m, (an >= 0.f ? tnmax : tnmin) * an);
    if (m < -1e29f) m = 0.f;
    Mk[k] = m;
}

// ---------------- k_S2: layer-2 softmax denominators (edge data only) ----------------
__global__ void k_S2() {
    int tid = threadIdx.x;
    int node = blockIdx.x * 8 + (tid >> 4);
    int k = tid & 15;
    if (node >= N_NODES) return;
    int a = g_off_src[node], b = g_off_src[node + 1];
    float Ap = g_Apos2[k], An = g_Aneg2[k], M = g_Mk2[k];
    float S = 0.f;
    int e = a;
    for (; e + 4 <= b; e += 4) {
        float t0 = __ldg(&g_es_t[e + 0]);
        float t1 = __ldg(&g_es_t[e + 1]);
        float t2 = __ldg(&g_es_t[e + 2]);
        float t3 = __ldg(&g_es_t[e + 3]);
        float e0 = __expf(fmaf(t0, (t0 >= 0.f) ? Ap : An, -M));
        float e1 = __expf(fmaf(t1, (t1 >= 0.f) ? Ap : An, -M));
        float e2 = __expf(fmaf(t2, (t2 >= 0.f) ? Ap : An, -M));
        float e3 = __expf(fmaf(t3, (t3 >= 0.f) ? Ap : An, -M));
        S += (e0 + e1) + (e2 + e3);
    }
    for (; e < b; e++) {
        float t = __ldg(&g_es_t[e]);
        S += __expf(fmaf(t, (t >= 0.f) ? Ap : An, -M));
    }
    g_invS2[(size_t)node * NCLS + k] = 1.f / (S + 1e-16f);
}

// ---------------- gemm1: two-tile smem GEMM ----------------
__global__ void k_gemm1(const float* __restrict__ x, const float* __restrict__ bias) {
    __shared__ __align__(16) float xs[G1_NB * G1_FC];   // [n][i]
    __shared__ __align__(16) float ws[G1_FC * HID];     // [i][k]
    int tid = threadIdx.x;
    int node0 = blockIdx.x * G1_NB;
    int k0 = (tid & 15) * 4, n0 = (tid >> 4) * 4;
    float acc[4][4] = {};
    for (int fc = 0; fc < F_IN; fc += G1_FC) {
        __syncthreads();
        {
            int n = tid >> 2;
            int node = node0 + n;
            const float4* src = (const float4*)&x[(size_t)node * F_IN + fc];
#pragma unroll
            for (int r = 0; r < 4; r++) {
                int i4 = (tid & 3) + r * 4;
                float4 v = (node < N_NODES) ? src[i4] : make_float4(0.f, 0.f, 0.f, 0.f);
                *(float4*)&xs[n * G1_FC + i4 * 4] = v;
            }
        }
        {
#pragma unroll
            for (int r = 0; r < 4; r++) {
                int idx = tid + r * 256;
                int i = idx >> 4, k4 = idx & 15;
                *(float4*)&ws[i * HID + k4 * 4] =
                    *(const float4*)&g_Wt1[(size_t)(fc + i) * HID + k4 * 4];
            }
        }
        __syncthreads();
#pragma unroll 2
        for (int i = 0; i < G1_FC; i += 4) {
            float4 w0 = *(const float4*)&ws[(i + 0) * HID + k0];
            float4 w1 = *(const float4*)&ws[(i + 1) * HID + k0];
            float4 w2 = *(const float4*)&ws[(i + 2) * HID + k0];
            float4 w3 = *(const float4*)&ws[(i + 3) * HID + k0];
#pragma unroll
            for (int j = 0; j < 4; j++) {
                float4 a = *(const float4*)&xs[(n0 + j) * G1_FC + i];
                acc[j][0] = fmaf(a.x, w0.x, acc[j][0]);
                acc[j][1] = fmaf(a.x, w0.y, acc[j][1]);
                acc[j][2] = fmaf(a.x, w0.z, acc[j][2]);
                acc[j][3] = fmaf(a.x, w0.w, acc[j][3]);
                acc[j][0] = fmaf(a.y, w1.x, acc[j][0]);
                acc[j][1] = fmaf(a.y, w1.y, acc[j][1]);
                acc[j][2] = fmaf(a.y, w1.z, acc[j][2]);
                acc[j][3] = fmaf(a.y, w1.w, acc[j][3]);
                acc[j][0] = fmaf(a.z, w2.x, acc[j][0]);
                acc[j][1] = fmaf(a.z, w2.y, acc[j][1]);
                acc[j][2] = fmaf(a.z, w2.z, acc[j][2]);
                acc[j][3] = fmaf(a.z, w2.w, acc[j][3]);
                acc[j][0] = fmaf(a.w, w3.x, acc[j][0]);
                acc[j][1] = fmaf(a.w, w3.y, acc[j][1]);
                acc[j][2] = fmaf(a.w, w3.z, acc[j][2]);
                acc[j][3] = fmaf(a.w, w3.w, acc[j][3]);
            }
        }
    }
    float4 bb = *(const float4*)&bias[k0];
#pragma unroll
    for (int j = 0; j < 4; j++) {
        int node = node0 + n0 + j;
        if (node < N_NODES) {
            float4 r;
            r.x = acc[j][0] + bb.x;
            r.y = acc[j][1] + bb.y;
            r.z = acc[j][2] + bb.z;
            r.w = acc[j][3] + bb.w;
            *(float4*)&g_x1[(size_t)node * HID + k0] = r;
        }
    }
}

// ---------------- gemm2: y2[n,k] = (sum_i h1[n,i]*W[k,i] + b[k]) * invS2[n,k] ----------------
__global__ void k_gemm2(const float* __restrict__ bias) {
    const int F = HID, K = NCLS;
    const int KH = K / 4;           // 4
    const int G  = 256 / KH;        // 64 groups of 2 nodes
    const int NB = G * 2;           // 128 nodes
    __shared__ __align__(16) float xs[NB * F];
    int tid = threadIdx.x;
    int node0 = blockIdx.x * NB;
    const int F4 = F / 4;
    for (int idx = tid; idx < NB * F4; idx += 256) {
        int nl = idx / F4, i4 = idx % F4;
        int node = node0 + nl;
        float4 v = (node < N_NODES) ? *(const float4*)&g_h1[(size_t)node * F + i4 * 4]
                                    : make_float4(0.f, 0.f, 0.f, 0.f);
        int g2 = nl >> 1, j = nl & 1;
        int base = (g2 * F + i4 * 4) * 2 + j;
        xs[base]     = v.x;
        xs[base + 2] = v.y;
        xs[base + 4] = v.z;
        xs[base + 6] = v.w;
    }
    __syncthreads();
    int k0 = (tid % KH) * 4, grp = tid / KH;
    const float2* xs2 = (const float2*)xs + (size_t)grp * F;
    float acc0[2] = {0, 0};
    float acc1[2] = {0, 0};
    float acc2[2] = {0, 0};
    float acc3[2] = {0, 0};
#pragma unroll 8
    for (int i = 0; i < F; i++) {
        float4 w = *(const float4*)&g_Wt2[i * K + k0];
        float2 a = xs2[i];
        acc0[0] = fmaf(a.x, w.x, acc0[0]); acc0[1] = fmaf(a.y, w.x, acc0[1]);
        acc1[0] = fmaf(a.x, w.y, acc1[0]); acc1[1] = fmaf(a.y, w.y, acc1[1]);
        acc2[0] = fmaf(a.x, w.z, acc2[0]); acc2[1] = fmaf(a.y, w.z, acc2[1]);
        acc3[0] = fmaf(a.x, w.w, acc3[0]); acc3[1] = fmaf(a.y, w.w, acc3[1]);
    }
    float4 bb = *(const float4*)&bias[k0];
#pragma unroll
    for (int j = 0; j < 2; j++) {
        int node = node0 + grp * 2 + j;
        if (node < N_NODES) {
            float4 s = *(const float4*)&g_invS2[(size_t)node * K + k0];
            float4 r;
            r.x = (acc0[j] + bb.x) * s.x;
            r.y = (acc1[j] + bb.y) * s.y;
            r.z = (acc2[j] + bb.z) * s.z;
            r.w = (acc3[j] + bb.w) * s.w;
            *(float4*)&g_y2[(size_t)node * K + k0] = r;
        }
    }
}

// ---------------- src pass (layer 1): y = x1 / S ----------------
__global__ void k_kc1() {
    const int K = HID;
    int tid = threadIdx.x;
    int node = blockIdx.x * 4 + tid / K;
    int k = tid % K;
    if (node >= N_NODES) return;
    int a = g_off_src[node], b = g_off_src[node + 1];
    float Ap = g_Apos1[k], An = g_Aneg1[k], M = g_Mk1[k];
    float S = 0.f;
    int e = a;
    for (; e + 4 <= b; e += 4) {
        float t0 = __ldg(&g_es_t[e + 0]);
        float t1 = __ldg(&g_es_t[e + 1]);
        float t2 = __ldg(&g_es_t[e + 2]);
        float t3 = __ldg(&g_es_t[e + 3]);
        float e0 = __expf(fmaf(t0, (t0 >= 0.f) ? Ap : An, -M));
        float e1 = __expf(fmaf(t1, (t1 >= 0.f) ? Ap : An, -M));
        float e2 = __expf(fmaf(t2, (t2 >= 0.f) ? Ap : An, -M));
        float e3 = __expf(fmaf(t3, (t3 >= 0.f) ? Ap : An, -M));
        S += (e0 + e1) + (e2 + e3);
    }
    for (; e < b; e++) {
        float t = __ldg(&g_es_t[e]);
        S += __expf(fmaf(t, (t >= 0.f) ? Ap : An, -M));
    }
    g_y1[(size_t)node * K + k] = g_x1[(size_t)node * K + k] / (S + 1e-16f);
}

// ---------------- dst pass: out[v,k] = sum_{e: dst=v} exp(t*c_k - Mk) * y[src,k] ----------------
template <int K, int MODE>  // MODE 0: ELU, MODE 1: log_softmax over K=16 lanes
__device__ void kd_body(const float* __restrict__ y, const float* __restrict__ Apos,
                        const float* __restrict__ Aneg, const float* __restrict__ Mk,
                        float* __restrict__ out) {
    const int NPB = 128 / K;
    int tid = threadIdx.x;
    int node = blockIdx.x * NPB + tid / K;
    int k = tid % K;
    if (node >= N_NODES) return;
    int a = g_off_dst[node], b = g_off_dst[node + 1];
    float Ap = Apos[k], An = Aneg[k], M = Mk[k];
    float acc = 0.f;
    int e = a;
    for (; e + 4 <= b; e += 4) {
        float2 ts0 = __ldg(&g_ed_ts[e + 0]);
        float2 ts1 = __ldg(&g_ed_ts[e + 1]);
        float2 ts2 = __ldg(&g_ed_ts[e + 2]);
        float2 ts3 = __ldg(&g_ed_ts[e + 3]);
        float yv0 = __ldg(&y[(size_t)__float_as_int(ts0.y) * K + k]);
        float yv1 = __ldg(&y[(size_t)__float_as_int(ts1.y) * K + k]);
        float yv2 = __ldg(&y[(size_t)__float_as_int(ts2.y) * K + k]);
        float yv3 = __ldg(&y[(size_t)__float_as_int(ts3.y) * K + k]);
        acc = fmaf(__expf(fmaf(ts0.x, (ts0.x >= 0.f) ? Ap : An, -M)), yv0, acc);
        acc = fmaf(__expf(fmaf(ts1.x, (ts1.x >= 0.f) ? Ap : An, -M)), yv1, acc);
        acc = fmaf(__expf(fmaf(ts2.x, (ts2.x >= 0.f) ? Ap : An, -M)), yv2, acc);
        acc = fmaf(__expf(fmaf(ts3.x, (ts3.x >= 0.f) ? Ap : An, -M)), yv3, acc);
    }
    for (; e < b; e++) {
        float2 ts = __ldg(&g_ed_ts[e]);
        float yv = __ldg(&y[(size_t)__float_as_int(ts.y) * K + k]);
        acc = fmaf(__expf(fmaf(ts.x, (ts.x >= 0.f) ? Ap : An, -M)), yv, acc);
    }
    if (MODE == 0) {
        out[(size_t)node * K + k] = (acc > 0.f) ? acc : expm1f(acc);
    } else {
        float m = acc;
        for (int o = 8; o; o >>= 1) m = fmaxf(m, __shfl_xor_sync(0xffffffffu, m, o, 16));
        float es = __expf(acc - m);
        float ssum = es;
        for (int o = 8; o; o >>= 1) ssum += __shfl_xor_sync(0xffffffffu, ssum, o, 16);
        out[(size_t)node * K + k] = acc - m - __logf(ssum);
    }
}
__global__ void k_kd1() { kd_body<HID, 0>(g_y1, g_Apos1, g_Aneg1, g_Mk1, g_h1); }
__global__ void k_kd2(float* __restrict__ out) { kd_body<NCLS, 1>(g_y2, g_Apos2, g_Aneg2, g_Mk2, out); }

// ---------------- launch ----------------
extern "C" void kernel_launch(void* const* d_in, const int* in_sizes, int n_in,
                              void* d_out, int out_size) {
    const float* x      = (const float*)d_in[0];
    const int*   ei32   = (const int*)d_in[1];   // int32 or int64 (detected on device)
    const float* wm     = (const float*)d_in[2];
    const float* lin1_w = (const float*)d_in[3];
    const float* lin1_b = (const float*)d_in[4];
    const float* m1w1   = (const float*)d_in[5];
    const float* m1w2   = (const float*)d_in[6];
    const float* lin2_w = (const float*)d_in[8];
    const float* lin2_b = (const float*)d_in[9];
    const float* m2w1   = (const float*)d_in[10];
    const float* m2w2   = (const float*)d_in[11];
    float* out = (float*)d_out;

    cudaStream_t s2;
    cudaStreamCreateWithFlags(&s2, cudaStreamNonBlocking);
    cudaEvent_t evFork, evScat, evS2;
    cudaEventCreateWithFlags(&evFork, cudaEventDisableTiming);
    cudaEventCreateWithFlags(&evScat, cudaEventDisableTiming);
    cudaEventCreateWithFlags(&evS2, cudaEventDisableTiming);

    // main: init (+detect) -> fork
    k_init<<<400, 512>>>(ei32);                                        // 1
    cudaEventRecord(evFork, 0);
    cudaStreamWaitEvent(s2, evFork, 0);

    k_transpose<<<(F_IN * HID + HID * NCLS + 255) / 256, 256>>>(lin1_w, lin2_w);  // 2

    // branch B issued FIRST (gets the machine; critical-path front)
    k_hist<<<EDGE_GRID, 256, 0, s2>>>(ei32, wm);                       // 3

    // main: gemm1 backfills around hist (4th launch = ncu window)
    k_gemm1<<<(N_NODES + G1_NB - 1) / G1_NB, 256>>>(x, lin1_b);        // 4

    // rest of branch B
    k_prep<<<1, HID + NCLS, 0, s2>>>(m1w1, m1w2, m2w1, m2w2);
    k_scan_part<<<SCAN_GRID, SCAN_TPB, 0, s2>>>();
    k_scan_mid<<<1, SCAN_TPB, 0, s2>>>();
    k_scan_final<<<SCAN_GRID, SCAN_TPB, 0, s2>>>();
    k_scatter<<<EDGE_GRID, 256, 0, s2>>>(ei32, wm);
    cudaEventRecord(evScat, s2);
    k_S2<<<(N_NODES + 7) / 8, 128, 0, s2>>>();
    cudaEventRecord(evS2, s2);

    // layer 1
    cudaStreamWaitEvent(0, evScat, 0);
    k_kc1<<<(N_NODES + 3) / 4, 256>>>();
    k_kd1<<<(N_NODES + 1) / 2, 128>>>();

    // layer 2 (kc2 folded into gemm2 epilogue via invS2 computed in branch B)
    cudaStreamWaitEvent(0, evS2, 0);
    k_gemm2<<<(N_NODES + 127) / 128, 256>>>(lin2_b);
    k_kd2<<<(N_NODES + 7) / 8, 128>>>(out);
}